// round 1
// baseline (speedup 1.0000x reference)
#include <cuda_runtime.h>
#include <math.h>

// Problem constants (fixed by the dataset): N=8, C=3, R=8, P1=P2=512, n_iter=3
#define P_    262144
#define P4_   65536        // P_/4 (float4 count per (n,r) plane)
#define EPS_  1e-10f

// ---- scratch layout in a __device__ global (no allocations allowed) ----
#define OFF_MEANX   0      // 24  : sum_p X[n,c,p]  (divide by P when used)
#define OFF_S      24      // 24  : current S[c*8+r]
#define OFF_F      48      // 64  : lazy scale f[n*8+r] applied to stored Dt
#define OFF_DTSUM 112      // 64  : sum_p of stored (unscaled) Dt
#define OFF_ACCSUM 176     // 64  : pass accumulator: sum_p Dt_new
#define OFF_GRAM  240      // 288 : pass accumulator: upper-tri Gram (36 per n)
#define OFF_XD    528      // 192 : pass accumulator: sum_p X[c]*Dt_new[r]
#define OFF_CNST  720      // 64  : per-(n,r) affine constant for the update
#define OFF_TAUD  784
#define OFF_GAMMA 785
#define OFF_LAM   786
#define OFF_SNRM  788      // 8   : column norms of S

__device__ float g_s[1024];

__device__ __forceinline__ int triIdx(int r, int r2) {   // r <= r2
    return r * 8 - (r * (r - 1)) / 2 + (r2 - r);
}
__device__ __forceinline__ float getc(const float4& v, int j) {
    return j == 0 ? v.x : j == 1 ? v.y : j == 2 ? v.z : v.w;
}
__device__ __forceinline__ void setc(float4& v, int j, float x) {
    if (j == 0) v.x = x; else if (j == 1) v.y = x; else if (j == 2) v.z = x; else v.w = x;
}

// ---------------------------------------------------------------------------
// k_init: zero scratch, load S / |gamma| / |lam|
// ---------------------------------------------------------------------------
__global__ void k_init(const float* __restrict__ S,
                       const float* __restrict__ gamma,
                       const float* __restrict__ lam) {
    int tid = threadIdx.x;
    for (int i = tid; i < 1024; i += blockDim.x) g_s[i] = 0.f;
    __syncthreads();
    if (tid < 24) g_s[OFF_S + tid] = S[tid];
    if (tid == 24) g_s[OFF_GAMMA] = fabsf(gamma[0]);
    if (tid == 25) g_s[OFF_LAM]   = fabsf(lam[0]);
}

// ---------------------------------------------------------------------------
// k_meanx: sum_p X[n,c,p] -> g_s[OFF_MEANX + n*3+c]   grid(32, 24), 256 thr
// ---------------------------------------------------------------------------
__global__ void __launch_bounds__(256) k_meanx(const float* __restrict__ X) {
    int y = blockIdx.y;                       // n*3+c
    const float4* Xp = reinterpret_cast<const float4*>(X + (size_t)y * P_);
    int base = blockIdx.x * 2048;
    float s = 0.f;
    #pragma unroll
    for (int l = 0; l < 8; l++) {
        float4 v = Xp[base + l * 256 + threadIdx.x];
        s += v.x + v.y + v.z + v.w;
    }
    #pragma unroll
    for (int o = 16; o; o >>= 1) s += __shfl_xor_sync(0xffffffffu, s, o);
    __shared__ float sw[8];
    if ((threadIdx.x & 31) == 0) sw[threadIdx.x >> 5] = s;
    __syncthreads();
    if (threadIdx.x == 0) {
        float t = 0.f;
        #pragma unroll
        for (int w = 0; w < 8; w++) t += sw[w];
        atomicAdd(&g_s[OFF_MEANX + y], t);
    }
}

// ---------------------------------------------------------------------------
// k_iterA: per-iteration prep. Zero accumulators; compute tau_D, S_nrm,
//          x0[n,c] = (meanX_sum + S·(f⊙Dtsum))/P, cnst[n,r] = tauD*b - thr.
// ---------------------------------------------------------------------------
__global__ void __launch_bounds__(128) k_iterA() {
    int tid = threadIdx.x;
    for (int i = tid; i < 544; i += blockDim.x) g_s[OFF_ACCSUM + i] = 0.f;
    __shared__ float sStS[64], sx0[24];
    __syncthreads();
    if (tid < 64) {                           // StS[r,r2]
        int r = tid >> 3, r2 = tid & 7;
        float a = 0.f;
        #pragma unroll
        for (int c = 0; c < 3; c++) a += g_s[OFF_S + c * 8 + r] * g_s[OFF_S + c * 8 + r2];
        sStS[tid] = a;
    }
    __syncthreads();
    if (tid == 0) {
        float s = 0.f;
        #pragma unroll
        for (int r = 0; r < 8; r++) s += sStS[r * 8 + r];
        g_s[OFF_TAUD] = 1.f / s;
    }
    if (tid >= 32 && tid < 40) {
        int r = tid - 32;
        g_s[OFF_SNRM + r] = sqrtf(sStS[r * 8 + r]);
    }
    if (tid >= 64 && tid < 88) {              // x0[n,c]
        int k = tid - 64, n = k / 3, c = k % 3;
        float acc = g_s[OFF_MEANX + k];
        #pragma unroll
        for (int r = 0; r < 8; r++)
            acc += g_s[OFF_S + c * 8 + r] * g_s[OFF_F + n * 8 + r] * g_s[OFF_DTSUM + n * 8 + r];
        sx0[k] = acc * (1.f / (float)P_);
    }
    __syncthreads();
    if (tid < 64) {                           // cnst[n,r]
        int n = tid >> 3, r = tid & 7;
        float tauD = g_s[OFF_TAUD];
        float b = 0.f;
        #pragma unroll
        for (int c = 0; c < 3; c++) b += g_s[OFF_S + c * 8 + r] * sx0[n * 3 + c];
        g_s[OFF_CNST + tid] = tauD * b - g_s[OFF_LAM] * g_s[OFF_GAMMA] * tauD * g_s[OFF_SNRM + r];
    }
}

// ---------------------------------------------------------------------------
// k_pass: fused D-update + prox + accumulation of sum / Gram / XD.
//   Dt_new[r] = relu( f[r]*d[r] - tauD * S^T (S (f⊙d) + x) + cnst[r] )
//   grid(128, 8), 128 threads, float4, in-place on the Dt region of d_out.
// ---------------------------------------------------------------------------
__global__ void __launch_bounds__(128) k_pass(const float* __restrict__ X,
                                              float* __restrict__ Dt, int first) {
    const int n = blockIdx.y;
    const int tid = threadIdx.x;

    float Sc[24], fr[8], cn[8];
    #pragma unroll
    for (int i = 0; i < 24; i++) Sc[i] = g_s[OFF_S + i];
    #pragma unroll
    for (int r = 0; r < 8; r++) {
        fr[r] = g_s[OFF_F + n * 8 + r];
        cn[r] = g_s[OFF_CNST + n * 8 + r];
    }
    const float tauD = g_s[OFF_TAUD];

    float a_sum[8], a_gram[36], a_xd[24];
    #pragma unroll
    for (int i = 0; i < 8; i++)  a_sum[i] = 0.f;
    #pragma unroll
    for (int i = 0; i < 36; i++) a_gram[i] = 0.f;
    #pragma unroll
    for (int i = 0; i < 24; i++) a_xd[i] = 0.f;

    const float4* Xp = reinterpret_cast<const float4*>(X + (size_t)n * 3 * P_);
    float4* Dp = reinterpret_cast<float4*>(Dt + (size_t)n * 8 * P_);

    #pragma unroll 1
    for (int l = 0; l < 4; l++) {
        int i4 = blockIdx.x * 512 + l * 128 + tid;
        float4 xv0 = Xp[i4], xv1 = Xp[i4 + P4_], xv2 = Xp[i4 + 2 * P4_];
        float4 dv[8];
        if (!first) {
            #pragma unroll
            for (int r = 0; r < 8; r++) dv[r] = Dp[i4 + r * P4_];
        }
        float4 ov[8];
        #pragma unroll
        for (int j = 0; j < 4; j++) {
            float x0 = getc(xv0, j), x1 = getc(xv1, j), x2 = getc(xv2, j);
            float de[8], v[8];
            float t0 = x0, t1 = x1, t2 = x2;
            if (!first) {
                #pragma unroll
                for (int r = 0; r < 8; r++) {
                    de[r] = fr[r] * getc(dv[r], j);
                    t0 += Sc[r] * de[r];
                    t1 += Sc[8 + r] * de[r];
                    t2 += Sc[16 + r] * de[r];
                }
            } else {
                #pragma unroll
                for (int r = 0; r < 8; r++) de[r] = 0.f;
            }
            #pragma unroll
            for (int r = 0; r < 8; r++) {
                float u = Sc[r] * t0 + Sc[8 + r] * t1 + Sc[16 + r] * t2;
                float val = de[r] + cn[r] - tauD * u;
                val = val > 0.f ? val : 0.f;
                v[r] = val;
                setc(ov[r], j, val);
                a_sum[r]      += val;
                a_xd[r]       += x0 * val;
                a_xd[8 + r]   += x1 * val;
                a_xd[16 + r]  += x2 * val;
            }
            int gi = 0;
            #pragma unroll
            for (int r = 0; r < 8; r++)
                #pragma unroll
                for (int r2 = r; r2 < 8; r2++) a_gram[gi++] += v[r] * v[r2];
        }
        #pragma unroll
        for (int r = 0; r < 8; r++) Dp[i4 + r * P4_] = ov[r];
    }

    // block reduction: warp shuffle -> smem -> one atomicAdd per value
    __shared__ float sred[4 * 68];
    int lane = tid & 31, wid = tid >> 5;
    #pragma unroll
    for (int k = 0; k < 8; k++) {
        float vv = a_sum[k];
        #pragma unroll
        for (int o = 16; o; o >>= 1) vv += __shfl_xor_sync(0xffffffffu, vv, o);
        if (lane == 0) sred[wid * 68 + k] = vv;
    }
    #pragma unroll
    for (int k = 0; k < 36; k++) {
        float vv = a_gram[k];
        #pragma unroll
        for (int o = 16; o; o >>= 1) vv += __shfl_xor_sync(0xffffffffu, vv, o);
        if (lane == 0) sred[wid * 68 + 8 + k] = vv;
    }
    #pragma unroll
    for (int k = 0; k < 24; k++) {
        float vv = a_xd[k];
        #pragma unroll
        for (int o = 16; o; o >>= 1) vv += __shfl_xor_sync(0xffffffffu, vv, o);
        if (lane == 0) sred[wid * 68 + 44 + k] = vv;
    }
    __syncthreads();
    if (tid < 68) {
        float s = sred[tid] + sred[68 + tid] + sred[136 + tid] + sred[204 + tid];
        int addr;
        if (tid < 8)       addr = OFF_ACCSUM + n * 8 + tid;
        else if (tid < 44) addr = OFF_GRAM + n * 36 + (tid - 8);
        else               addr = OFF_XD + n * 24 + (tid - 44);
        atomicAdd(&g_s[addr], s);
    }
}

// ---------------------------------------------------------------------------
// k_iterB: prox scale scl, x0 (S-update), tau_S, G, S_grad, S prox+renorm,
//          new lazy scale f. On last iteration also writes x0 and S outputs.
// ---------------------------------------------------------------------------
__global__ void __launch_bounds__(512) k_iterB(float* __restrict__ out, int last) {
    int tid = threadIdx.x;
    __shared__ float s_scl[64], s_sums[64], s_gt[64], s_tr[64];
    __shared__ float s_gram[8][8][8], s_x0[24], s_G[192], s_Sg[24], s_n3[8];
    __shared__ float s_tauS;
    float lam = g_s[OFF_LAM], gam = g_s[OFF_GAMMA], tauD = g_s[OFF_TAUD];

    if (tid < 64) {
        int n = tid >> 3, r = tid & 7;
        float gu = g_s[OFF_GRAM + n * 36 + triIdx(r, r)];
        float L2 = sqrtf(gu);
        float t = L2 - lam * tauD * g_s[OFF_SNRM + r];
        float scl = (t > 0.f ? t : 0.f) / L2 + EPS_;     // faithful to source
        s_scl[tid] = scl;
        float su = scl * g_s[OFF_ACCSUM + tid];
        s_sums[tid] = su;
        s_gt[tid] = gam * su + scl * L2;                 // gamma*sum|Dt| + ||Dt||
        s_tr[tid] = scl * scl * gu;                      // trace contrib
    }
    __syncthreads();
    {
        int n = tid >> 6, r = (tid >> 3) & 7, r2 = tid & 7;
        int lo = min(r, r2), hi = max(r, r2);
        s_gram[n][r][r2] = s_scl[n * 8 + r] * s_scl[n * 8 + r2] *
                           g_s[OFF_GRAM + n * 36 + triIdx(lo, hi)];
    }
    __syncthreads();
    if (tid < 24) {                                      // x0 (S-update, pre-update S)
        int n = tid / 3, c = tid % 3;
        float a = g_s[OFF_MEANX + tid];
        #pragma unroll
        for (int r = 0; r < 8; r++) a += g_s[OFF_S + c * 8 + r] * s_sums[n * 8 + r];
        a *= (1.f / (float)P_);
        s_x0[tid] = a;
        if (last) out[tid] = a;
    }
    if (tid == 64) {
        float s = 0.f;
        for (int k = 0; k < 64; k++) s += s_tr[k];
        s_tauS = 8.f / s;                                // 1/mean_n(trace)
    }
    __syncthreads();
    if (tid < 192) {                                     // G[n,c,r]
        int n = tid / 24, c = (tid / 8) % 3, r = tid & 7;
        float g = s_scl[n * 8 + r] * g_s[OFF_XD + n * 24 + c * 8 + r];
        #pragma unroll
        for (int r2 = 0; r2 < 8; r2++) g += g_s[OFF_S + c * 8 + r2] * s_gram[n][r2][r];
        g -= s_x0[n * 3 + c] * s_sums[n * 8 + r];
        s_G[tid] = g;
    }
    __syncthreads();
    if (tid < 24) {                                      // S_grad[c,r]
        int c = tid / 8, r = tid & 7;
        float mg = 0.f;
        #pragma unroll
        for (int n = 0; n < 8; n++) mg += s_G[n * 24 + c * 8 + r];
        mg *= 0.125f;
        s_Sg[tid] = g_s[OFF_S + c * 8 + r] - s_tauS * mg;
    }
    __syncthreads();
    if (tid < 8) {                                       // S column prox + renorm
        int r = tid;
        float dn = 0.f;
        #pragma unroll
        for (int n = 0; n < 8; n++) dn += s_gt[n * 8 + r];
        dn *= 0.125f;                                    // Dt_nrm[r]
        float n2 = 0.f;
        #pragma unroll
        for (int c = 0; c < 3; c++) n2 += s_Sg[c * 8 + r] * s_Sg[c * 8 + r];
        n2 = sqrtf(n2);
        float t = n2 - lam * s_tauS * dn;
        float sclS = (t > 0.f ? t : 0.f) / (n2 + EPS_);
        float sn[3]; float n3 = 0.f;
        #pragma unroll
        for (int c = 0; c < 3; c++) { sn[c] = s_Sg[c * 8 + r] * sclS; n3 += sn[c] * sn[c]; }
        n3 = sqrtf(n3);
        s_n3[r] = n3;
        float inv = 1.f / (n3 + EPS_);
        #pragma unroll
        for (int c = 0; c < 3; c++) {
            float nv = sn[c] * inv;
            g_s[OFF_S + c * 8 + r] = nv;
            if (last) out[24 + c * 8 + r] = nv;
        }
    }
    __syncthreads();
    if (tid < 64) {                                      // new lazy scale + Dtsum
        int r = tid & 7;
        g_s[OFF_F + tid] = s_scl[tid] * (s_n3[r] + EPS_);
        g_s[OFF_DTSUM + tid] = g_s[OFF_ACCSUM + tid];
    }
}

// ---------------------------------------------------------------------------
// k_scale: final in-place Dt *= f[n,r]   grid(64, 64), 256 threads
// ---------------------------------------------------------------------------
__global__ void __launch_bounds__(256) k_scale(float* __restrict__ Dt) {
    int y = blockIdx.y;                                  // n*8+r
    float f = g_s[OFF_F + y];
    float4* D = reinterpret_cast<float4*>(Dt + (size_t)y * P_);
    int base = blockIdx.x * 1024;
    #pragma unroll
    for (int l = 0; l < 4; l++) {
        int i = base + l * 256 + threadIdx.x;
        float4 v = D[i];
        v.x *= f; v.y *= f; v.z *= f; v.w *= f;
        D[i] = v;
    }
}

// ---------------------------------------------------------------------------
extern "C" void kernel_launch(void* const* d_in, const int* in_sizes, int n_in,
                              void* d_out, int out_size) {
    const float* X     = (const float*)d_in[0];
    const float* S     = (const float*)d_in[1];
    const float* gamma = (const float*)d_in[2];
    const float* lam   = (const float*)d_in[3];
    float* out = (float*)d_out;
    float* Dt  = out + 48;                               // Dt region of output

    k_init<<<1, 256>>>(S, gamma, lam);
    k_meanx<<<dim3(32, 24), 256>>>(X);
    for (int it = 0; it < 3; it++) {
        k_iterA<<<1, 128>>>();
        k_pass<<<dim3(128, 8), 128>>>(X, Dt, it == 0 ? 1 : 0);
        k_iterB<<<1, 512>>>(out, it == 2 ? 1 : 0);
    }
    k_scale<<<dim3(64, 64), 256>>>(Dt);
}